// round 1
// baseline (speedup 1.0000x reference)
#include <cuda_runtime.h>

#define EMB  1024
#define NH   16
#define HD   64
#define SEQ  2048
#define NB   4
#define MTOT (NB * SEQ)   // 8192
#define SP   65           // padded shared stride for attention tiles

// Scratch (allocation-free rule: __device__ globals)
__device__ float g_q[(size_t)NB * NH * SEQ * HD];
__device__ float g_k[(size_t)NB * NH * SEQ * HD];
__device__ float g_v[(size_t)NB * NH * SEQ * HD];
__device__ float g_attn[(size_t)MTOT * EMB];

// ---------------------------------------------------------------------------
// C[m,n] = sum_k A[m,k] * B[n,k]   (both operands K-major; "NT" GEMM)
// 128x128 block tile, BK=8, 256 threads, 8x8 micro-tile per thread.
// MODE 0: C row-major [M, EMB].  MODE 1: scatter to [B, H, S, D] layout.
// ---------------------------------------------------------------------------
template <int MODE>
__device__ __forceinline__ void gemm_body(const float* __restrict__ A,
                                          const float* __restrict__ B,
                                          float* __restrict__ C)
{
    __shared__ float As[8][128];
    __shared__ float Bs[8][128];

    const int tid  = threadIdx.x;
    const int m0   = blockIdx.x * 128;
    const int n0   = blockIdx.y * 128;
    const int lrow = tid >> 1;          // 0..127
    const int lc4  = (tid & 1) * 4;     // 0 or 4
    const int ra   = (tid >> 4) * 4;    // 0..60
    const int ca   = (tid & 15) * 4;    // 0..60

    float acc[8][8];
#pragma unroll
    for (int i = 0; i < 8; i++)
#pragma unroll
        for (int j = 0; j < 8; j++) acc[i][j] = 0.f;

    const float* Ap = A + (size_t)(m0 + lrow) * EMB + lc4;
    const float* Bp = B + (size_t)(n0 + lrow) * EMB + lc4;

    for (int k0 = 0; k0 < EMB; k0 += 8) {
        float4 a4 = *(const float4*)(Ap + k0);
        float4 b4 = *(const float4*)(Bp + k0);
        As[lc4 + 0][lrow] = a4.x; As[lc4 + 1][lrow] = a4.y;
        As[lc4 + 2][lrow] = a4.z; As[lc4 + 3][lrow] = a4.w;
        Bs[lc4 + 0][lrow] = b4.x; Bs[lc4 + 1][lrow] = b4.y;
        Bs[lc4 + 2][lrow] = b4.z; Bs[lc4 + 3][lrow] = b4.w;
        __syncthreads();
#pragma unroll
        for (int kk = 0; kk < 8; kk++) {
            float ar[8], br[8];
            float4 t;
            t = *(const float4*)&As[kk][ra];        ar[0]=t.x; ar[1]=t.y; ar[2]=t.z; ar[3]=t.w;
            t = *(const float4*)&As[kk][64 + ra];   ar[4]=t.x; ar[5]=t.y; ar[6]=t.z; ar[7]=t.w;
            t = *(const float4*)&Bs[kk][ca];        br[0]=t.x; br[1]=t.y; br[2]=t.z; br[3]=t.w;
            t = *(const float4*)&Bs[kk][64 + ca];   br[4]=t.x; br[5]=t.y; br[6]=t.z; br[7]=t.w;
#pragma unroll
            for (int i = 0; i < 8; i++)
#pragma unroll
                for (int j = 0; j < 8; j++)
                    acc[i][j] += ar[i] * br[j];
        }
        __syncthreads();
    }

#pragma unroll
    for (int i = 0; i < 8; i++) {
        const int r = m0 + ((i < 4) ? (ra + i) : (60 + ra + i));
#pragma unroll
        for (int jq = 0; jq < 2; jq++) {
            const int c = n0 + ca + jq * 64;
            float4 v = make_float4(acc[i][jq*4+0], acc[i][jq*4+1],
                                   acc[i][jq*4+2], acc[i][jq*4+3]);
            if (MODE == 0) {
                *(float4*)&C[(size_t)r * EMB + c] = v;
            } else {
                const int b = r >> 11, s = r & (SEQ - 1);
                const int h = c >> 6,  d = c & (HD - 1);
                *(float4*)&C[((((size_t)b * NH + h) * SEQ + s) << 6) + d] = v;
            }
        }
    }
}

__global__ void __launch_bounds__(256)
qkv_kernel(const float* __restrict__ x,
           const float* __restrict__ wq,
           const float* __restrict__ wk,
           const float* __restrict__ wv)
{
    const int z = blockIdx.z;
    const float* W = (z == 0) ? wq : ((z == 1) ? wk : wv);
    float* O       = (z == 0) ? g_q : ((z == 1) ? g_k : g_v);
    gemm_body<1>(x, W, O);
}

__global__ void __launch_bounds__(256)
oproj_kernel(const float* __restrict__ wo, float* __restrict__ out)
{
    gemm_body<0>(g_attn, wo, out);
}

// ---------------------------------------------------------------------------
// Flash attention: one block = 64 q-rows of one (b, h). Online softmax.
// 256 threads, 4x4 micro-tiles of the 64x64 score tile.
// Shared: Qs, Ks (reused for P), Vs; stride SP=65 to break bank conflicts.
// ---------------------------------------------------------------------------
__global__ void __launch_bounds__(256)
attn_kernel(const int* __restrict__ mask)
{
    extern __shared__ float sh[];
    float* Qs = sh;                 // 64 x SP
    float* Ks = sh + 64 * SP;       // 64 x SP (K tile, then P tile)
    float* Vs = sh + 2 * 64 * SP;   // 64 x SP

    const int tid = threadIdx.x;
    const int tx  = tid & 15;       // col group
    const int ty  = tid >> 4;       // row group
    const int qt  = blockIdx.x;
    const int h   = blockIdx.y;
    const int b   = blockIdx.z;
    const int qm0 = qt * 64;

    const float* Qg = g_q + (((size_t)b * NH + h) * SEQ + qm0) * HD;
    const float* Kg = g_k + (((size_t)b * NH + h) * SEQ) * HD;
    const float* Vg = g_v + (((size_t)b * NH + h) * SEQ) * HD;
    const int* mrow = mask + b * SEQ;

    // Load Q tile (synced by the barrier after the first K/V load)
    for (int i = tid; i < 64 * 16; i += 256) {
        const int r = i >> 4, c4 = (i & 15) << 2;
        float4 v = *(const float4*)(Qg + (size_t)r * HD + c4);
        float* q = &Qs[r * SP + c4];
        q[0] = v.x; q[1] = v.y; q[2] = v.z; q[3] = v.w;
    }

    float m_i[4], l_i[4], accO[4][4];
#pragma unroll
    for (int i = 0; i < 4; i++) {
        m_i[i] = -1e30f; l_i[i] = 0.f;
#pragma unroll
        for (int j = 0; j < 4; j++) accO[i][j] = 0.f;
    }
    const float scale = 0.125f;   // 1/sqrt(64)

    for (int t = 0; t <= qt; t++) {
        const int kn0 = t * 64;
        for (int i = tid; i < 64 * 16; i += 256) {
            const int r = i >> 4, c4 = (i & 15) << 2;
            float4 kv = *(const float4*)(Kg + (size_t)(kn0 + r) * HD + c4);
            float4 vv = *(const float4*)(Vg + (size_t)(kn0 + r) * HD + c4);
            float* kd = &Ks[r * SP + c4];
            kd[0] = kv.x; kd[1] = kv.y; kd[2] = kv.z; kd[3] = kv.w;
            float* vd = &Vs[r * SP + c4];
            vd[0] = vv.x; vd[1] = vv.y; vd[2] = vv.z; vd[3] = vv.w;
        }
        __syncthreads();

        // S = Q K^T (contraction over d)
        float s[4][4];
#pragma unroll
        for (int i = 0; i < 4; i++)
#pragma unroll
            for (int j = 0; j < 4; j++) s[i][j] = 0.f;
#pragma unroll 4
        for (int kk = 0; kk < 64; kk++) {
            float ar[4], br[4];
#pragma unroll
            for (int i = 0; i < 4; i++) ar[i] = Qs[(ty * 4 + i) * SP + kk];
#pragma unroll
            for (int j = 0; j < 4; j++) br[j] = Ks[(tx * 4 + j) * SP + kk];
#pragma unroll
            for (int i = 0; i < 4; i++)
#pragma unroll
                for (int j = 0; j < 4; j++)
                    s[i][j] += ar[i] * br[j];
        }

        // scale + causal + pad mask
        int mv[4];
#pragma unroll
        for (int j = 0; j < 4; j++) mv[j] = mrow[kn0 + tx * 4 + j];
#pragma unroll
        for (int i = 0; i < 4; i++) {
            const int qr = qm0 + ty * 4 + i;
#pragma unroll
            for (int j = 0; j < 4; j++) {
                const int kc = kn0 + tx * 4 + j;
                float v = s[i][j] * scale;
                if (kc > qr || mv[j] == 0) v = -1e30f;
                s[i][j] = v;
            }
        }

        // online softmax (row groups = 16 lanes within a half-warp)
#pragma unroll
        for (int i = 0; i < 4; i++) {
            float rmax = fmaxf(fmaxf(s[i][0], s[i][1]), fmaxf(s[i][2], s[i][3]));
#pragma unroll
            for (int o = 8; o >= 1; o >>= 1)
                rmax = fmaxf(rmax, __shfl_xor_sync(0xffffffffu, rmax, o));
            const float mn = fmaxf(m_i[i], rmax);
            const float alpha = __expf(m_i[i] - mn);
            m_i[i] = mn;
            float su = 0.f;
#pragma unroll
            for (int j = 0; j < 4; j++) {
                const float p = __expf(s[i][j] - mn);
                s[i][j] = p;
                su += p;
            }
#pragma unroll
            for (int o = 8; o >= 1; o >>= 1)
                su += __shfl_xor_sync(0xffffffffu, su, o);
            l_i[i] = l_i[i] * alpha + su;
#pragma unroll
            for (int j = 0; j < 4; j++) accO[i][j] *= alpha;
        }

        __syncthreads();            // done reading K tile
#pragma unroll
        for (int i = 0; i < 4; i++)
#pragma unroll
            for (int j = 0; j < 4; j++)
                Ks[(ty * 4 + i) * SP + tx * 4 + j] = s[i][j];
        __syncthreads();

        // O += P V
#pragma unroll 4
        for (int c = 0; c < 64; c++) {
            float pr[4], vr[4];
#pragma unroll
            for (int i = 0; i < 4; i++) pr[i] = Ks[(ty * 4 + i) * SP + c];
#pragma unroll
            for (int j = 0; j < 4; j++) vr[j] = Vs[c * SP + tx * 4 + j];
#pragma unroll
            for (int i = 0; i < 4; i++)
#pragma unroll
                for (int j = 0; j < 4; j++)
                    accO[i][j] += pr[i] * vr[j];
        }
        __syncthreads();
    }

    // epilogue: write [B, S, E] for the output projection
#pragma unroll
    for (int i = 0; i < 4; i++) {
        const float inv = 1.0f / l_i[i];
        const int r = qm0 + ty * 4 + i;
        float4 o4 = make_float4(accO[i][0] * inv, accO[i][1] * inv,
                                accO[i][2] * inv, accO[i][3] * inv);
        *(float4*)&g_attn[((size_t)b * SEQ + r) * EMB + h * HD + tx * 4] = o4;
    }
}

// ---------------------------------------------------------------------------
extern "C" void kernel_launch(void* const* d_in, const int* in_sizes, int n_in,
                              void* d_out, int out_size)
{
    const float* x    = (const float*)d_in[0];
    const int*   mask = (const int*)d_in[1];
    const float* wq   = (const float*)d_in[2];
    const float* wk   = (const float*)d_in[3];
    const float* wv   = (const float*)d_in[4];
    const float* wo   = (const float*)d_in[5];
    float* out = (float*)d_out;

    // 1) Q/K/V projections -> [B, H, S, D]
    qkv_kernel<<<dim3(MTOT / 128, EMB / 128, 3), 256>>>(x, wq, wk, wv);

    // 2) causal flash attention -> g_attn [B, S, E]
    const int shbytes = 3 * 64 * SP * (int)sizeof(float);   // 49920 B
    cudaFuncSetAttribute(attn_kernel,
                         cudaFuncAttributeMaxDynamicSharedMemorySize, shbytes);
    attn_kernel<<<dim3(SEQ / 64, NH, NB), 256, shbytes>>>(mask);

    // 3) output projection -> d_out [B, S, E]
    oproj_kernel<<<dim3(MTOT / 128, EMB / 128, 1), 256>>>(wo, out);
}

// round 4
// speedup vs baseline: 1.5526x; 1.5526x over previous
#include <cuda_runtime.h>
#include <cuda_bf16.h>
#include <cstdint>

#define EMB  1024
#define NH   16
#define HD   64
#define SEQ  2048
#define NB   4
#define MTOT (NB * SEQ)   // 8192
#define SP   65

// ---------------- scratch (__device__ globals; no allocs allowed) ----------
__device__ float g_q[(size_t)NB * NH * SEQ * HD];
__device__ float g_k[(size_t)NB * NH * SEQ * HD];
__device__ float g_v[(size_t)NB * NH * SEQ * HD];
__device__ float g_attn[(size_t)MTOT * EMB];
__device__ __nv_bfloat16 g_xh[(size_t)MTOT * EMB], g_xl[(size_t)MTOT * EMB];
__device__ __nv_bfloat16 g_ah[(size_t)MTOT * EMB], g_al[(size_t)MTOT * EMB];
__device__ __nv_bfloat16 g_wh[4][(size_t)EMB * EMB], g_wl[4][(size_t)EMB * EMB];

// ---------------- helpers ---------------------------------------------------
__device__ __forceinline__ uint32_t smem_u32(const void* p) {
    uint32_t a;
    asm("{ .reg .u64 t; cvta.to.shared.u64 t, %1; cvt.u32.u64 %0, t; }"
        : "=r"(a) : "l"(p));
    return a;
}
__device__ __forceinline__ void ldsm4(uint32_t* r, uint32_t addr) {
    asm volatile("ldmatrix.sync.aligned.m8n8.x4.shared.b16 {%0,%1,%2,%3}, [%4];"
                 : "=r"(r[0]), "=r"(r[1]), "=r"(r[2]), "=r"(r[3]) : "r"(addr));
}
__device__ __forceinline__ void mma16816(float* c, const uint32_t* a,
                                         uint32_t b0, uint32_t b1) {
    asm volatile(
        "mma.sync.aligned.m16n8k16.row.col.f32.bf16.bf16.f32 "
        "{%0,%1,%2,%3}, {%4,%5,%6,%7}, {%8,%9}, {%0,%1,%2,%3};"
        : "+f"(c[0]), "+f"(c[1]), "+f"(c[2]), "+f"(c[3])
        : "r"(a[0]), "r"(a[1]), "r"(a[2]), "r"(a[3]), "r"(b0), "r"(b1));
}

// ---------------- hi/lo split prepass --------------------------------------
__global__ void __launch_bounds__(256)
split_kernel(const float* __restrict__ in, int which, int n)
{
    __nv_bfloat16 *hp, *lp;
    const float* src = in;
    if (which == 0)       { hp = g_xh; lp = g_xl; }
    else if (which <= 4)  { hp = g_wh[which - 1]; lp = g_wl[which - 1]; }
    else                  { hp = g_ah; lp = g_al; src = g_attn; }

    int i = (blockIdx.x * 256 + threadIdx.x) * 4;
    if (i >= n) return;
    float4 v = *(const float4*)(src + i);
    __nv_bfloat16 h0 = __float2bfloat16(v.x);
    __nv_bfloat16 h1 = __float2bfloat16(v.y);
    __nv_bfloat16 h2 = __float2bfloat16(v.z);
    __nv_bfloat16 h3 = __float2bfloat16(v.w);
    __nv_bfloat16 l0 = __float2bfloat16(v.x - __bfloat162float(h0));
    __nv_bfloat16 l1 = __float2bfloat16(v.y - __bfloat162float(h1));
    __nv_bfloat16 l2 = __float2bfloat16(v.z - __bfloat162float(h2));
    __nv_bfloat16 l3 = __float2bfloat16(v.w - __bfloat162float(h3));
    __nv_bfloat162* hq = (__nv_bfloat162*)(hp + i);
    __nv_bfloat162* lq = (__nv_bfloat162*)(lp + i);
    hq[0] = __nv_bfloat162(h0, h1); hq[1] = __nv_bfloat162(h2, h3);
    lq[0] = __nv_bfloat162(l0, l1); lq[1] = __nv_bfloat162(l2, l3);
}

// ---------------- HMMA split-bf16 GEMM --------------------------------------
// C[m,n] = sum_k A[m,k]*B[n,k].  128x128 CTA tile, 8 warps of 32x64, BK=32.
// MODE 0: C row-major [*, EMB].  MODE 1: scatter to [B,H,S,D].
#define TS 40   // padded smem stride in halves (32 k + 8 pad): conflict-free ldmatrix

template <int MODE>
__device__ void hmma_gemm(const __nv_bfloat16* __restrict__ Ah_,
                          const __nv_bfloat16* __restrict__ Al_,
                          const __nv_bfloat16* __restrict__ Bh_,
                          const __nv_bfloat16* __restrict__ Bl_,
                          float* __restrict__ C)
{
    __shared__ __nv_bfloat16 sAh[128][TS], sAl[128][TS];
    __shared__ __nv_bfloat16 sBh[128][TS], sBl[128][TS];

    const int tid   = threadIdx.x;
    const int lane  = tid & 31;
    const int wid   = tid >> 5;
    const int warpM = wid & 3;      // 4 warps along M: 32 rows each
    const int warpN = wid >> 2;     // 2 warps along N: 64 cols each
    const int m0 = blockIdx.x * 128;
    const int n0 = blockIdx.y * 128;

    const uint32_t bAh = smem_u32(&sAh[0][0]);
    const uint32_t bAl = smem_u32(&sAl[0][0]);
    const uint32_t bBh = smem_u32(&sBh[0][0]);
    const uint32_t bBl = smem_u32(&sBl[0][0]);

    float acc[2][8][4];
#pragma unroll
    for (int mt = 0; mt < 2; mt++)
#pragma unroll
        for (int nt = 0; nt < 8; nt++)
#pragma unroll
            for (int e = 0; e < 4; e++) acc[mt][nt][e] = 0.f;

    // ldmatrix lane addressing (within a 16x16 A tile / 16x16 B block)
    const int a_r = lane & 15;               // row within tile
    const int a_c = (lane >> 4) << 3;        // 0 or 8 (k offset)
    const int b_r = ((lane >> 4) << 3) + (lane & 7);   // n offset within 16
    const int b_c = ((lane >> 3) & 1) << 3;            // 0 or 8 (k offset)

    for (int ch = 0; ch < EMB / 32; ch++) {
        const int k0 = ch * 32;
        __syncthreads();
        // fill 4 tiles: 128 rows x 32 halves each (uint4 = 8 halves)
#pragma unroll
        for (int u = tid; u < 512; u += 256) {
            const int r = u >> 2, c = (u & 3) << 3;
            *(uint4*)&sAh[r][c] = *(const uint4*)(Ah_ + (size_t)(m0 + r) * EMB + k0 + c);
            *(uint4*)&sAl[r][c] = *(const uint4*)(Al_ + (size_t)(m0 + r) * EMB + k0 + c);
            *(uint4*)&sBh[r][c] = *(const uint4*)(Bh_ + (size_t)(n0 + r) * EMB + k0 + c);
            *(uint4*)&sBl[r][c] = *(const uint4*)(Bl_ + (size_t)(n0 + r) * EMB + k0 + c);
        }
        __syncthreads();

#pragma unroll
        for (int ks = 0; ks < 2; ks++) {
            const int kb = ks << 4;
            uint32_t ah[2][4], al[2][4];
#pragma unroll
            for (int mt = 0; mt < 2; mt++) {
                const uint32_t off =
                    (uint32_t)((warpM * 32 + mt * 16 + a_r) * TS + kb + a_c) * 2;
                ldsm4(ah[mt], bAh + off);
                ldsm4(al[mt], bAl + off);
            }
#pragma unroll
            for (int ng = 0; ng < 4; ng++) {       // groups of 2 n-tiles (16 cols)
                const uint32_t off =
                    (uint32_t)((warpN * 64 + ng * 16 + b_r) * TS + kb + b_c) * 2;
                uint32_t bh[4], bl[4];
                ldsm4(bh, bBh + off);
                ldsm4(bl, bBl + off);
#pragma unroll
                for (int mt = 0; mt < 2; mt++) {
                    mma16816(acc[mt][2 * ng],     ah[mt], bh[0], bh[1]);
                    mma16816(acc[mt][2 * ng],     ah[mt], bl[0], bl[1]);
                    mma16816(acc[mt][2 * ng],     al[mt], bh[0], bh[1]);
                    mma16816(acc[mt][2 * ng + 1], ah[mt], bh[2], bh[3]);
                    mma16816(acc[mt][2 * ng + 1], ah[mt], bl[2], bl[3]);
                    mma16816(acc[mt][2 * ng + 1], al[mt], bh[2], bh[3]);
                }
            }
        }
    }

    // epilogue: c0,c1 -> (row, col..col+1); c2,c3 -> (row+8, col..col+1)
#pragma unroll
    for (int mt = 0; mt < 2; mt++) {
#pragma unroll
        for (int nt = 0; nt < 8; nt++) {
            const int row = m0 + warpM * 32 + mt * 16 + (lane >> 2);
            const int col = n0 + warpN * 64 + nt * 8 + ((lane & 3) << 1);
#pragma unroll
            for (int half = 0; half < 2; half++) {
                const int r = row + half * 8;
                float2 v = make_float2(acc[mt][nt][2 * half],
                                       acc[mt][nt][2 * half + 1]);
                if (MODE == 0) {
                    *(float2*)&C[(size_t)r * EMB + col] = v;
                } else {
                    const int b = r >> 11, s = r & (SEQ - 1);
                    const int h = col >> 6, d = col & (HD - 1);
                    *(float2*)&C[((((size_t)b * NH + h) * SEQ + s) << 6) + d] = v;
                }
            }
        }
    }
}

__global__ void __launch_bounds__(256) qkv_mma_kernel()
{
    const int z = blockIdx.z;
    float* C = (z == 0) ? g_q : ((z == 1) ? g_k : g_v);
    hmma_gemm<1>(g_xh, g_xl, g_wh[z], g_wl[z], C);
}
__global__ void __launch_bounds__(256) oproj_mma_kernel(float* __restrict__ out)
{
    hmma_gemm<0>(g_ah, g_al, g_wh[3], g_wl[3], out);
}

// ---------------- flash attention (fp32, known good) ------------------------
__global__ void __launch_bounds__(256)
attn_kernel(const int* __restrict__ mask)
{
    extern __shared__ float sh[];
    float* Qs = sh;
    float* Ks = sh + 64 * SP;
    float* Vs = sh + 2 * 64 * SP;

    const int tid = threadIdx.x;
    const int tx  = tid & 15;
    const int ty  = tid >> 4;
    const int qt  = blockIdx.x;
    const int h   = blockIdx.y;
    const int b   = blockIdx.z;
    const int qm0 = qt * 64;

    const float* Qg = g_q + (((size_t)b * NH + h) * SEQ + qm0) * HD;
    const float* Kg = g_k + (((size_t)b * NH + h) * SEQ) * HD;
    const float* Vg = g_v + (((size_t)b * NH + h) * SEQ) * HD;
    const int* mrow = mask + b * SEQ;

    for (int i = tid; i < 64 * 16; i += 256) {
        const int r = i >> 4, c4 = (i & 15) << 2;
        float4 v = *(const float4*)(Qg + (size_t)r * HD + c4);
        float* q = &Qs[r * SP + c4];
        q[0] = v.x; q[1] = v.y; q[2] = v.z; q[3] = v.w;
    }

    float m_i[4], l_i[4], accO[4][4];
#pragma unroll
    for (int i = 0; i < 4; i++) {
        m_i[i] = -1e30f; l_i[i] = 0.f;
#pragma unroll
        for (int j = 0; j < 4; j++) accO[i][j] = 0.f;
    }
    const float scale = 0.125f;

    for (int t = 0; t <= qt; t++) {
        const int kn0 = t * 64;
        for (int i = tid; i < 64 * 16; i += 256) {
            const int r = i >> 4, c4 = (i & 15) << 2;
            float4 kv = *(const float4*)(Kg + (size_t)(kn0 + r) * HD + c4);
            float4 vv = *(const float4*)(Vg + (size_t)(kn0 + r) * HD + c4);
            float* kd = &Ks[r * SP + c4];
            kd[0] = kv.x; kd[1] = kv.y; kd[2] = kv.z; kd[3] = kv.w;
            float* vd = &Vs[r * SP + c4];
            vd[0] = vv.x; vd[1] = vv.y; vd[2] = vv.z; vd[3] = vv.w;
        }
        __syncthreads();

        float s[4][4];
#pragma unroll
        for (int i = 0; i < 4; i++)
#pragma unroll
            for (int j = 0; j < 4; j++) s[i][j] = 0.f;
#pragma unroll 4
        for (int kk = 0; kk < 64; kk++) {
            float ar[4], br[4];
#pragma unroll
            for (int i = 0; i < 4; i++) ar[i] = Qs[(ty * 4 + i) * SP + kk];
#pragma unroll
            for (int j = 0; j < 4; j++) br[j] = Ks[(tx * 4 + j) * SP + kk];
#pragma unroll
            for (int i = 0; i < 4; i++)
#pragma unroll
                for (int j = 0; j < 4; j++)
                    s[i][j] += ar[i] * br[j];
        }

        int mv[4];
#pragma unroll
        for (int j = 0; j < 4; j++) mv[j] = mrow[kn0 + tx * 4 + j];
#pragma unroll
        for (int i = 0; i < 4; i++) {
            const int qr = qm0 + ty * 4 + i;
#pragma unroll
            for (int j = 0; j < 4; j++) {
                const int kc = kn0 + tx * 4 + j;
                float v = s[i][j] * scale;
                if (kc > qr || mv[j] == 0) v = -1e30f;
                s[i][j] = v;
            }
        }

#pragma unroll
        for (int i = 0; i < 4; i++) {
            float rmax = fmaxf(fmaxf(s[i][0], s[i][1]), fmaxf(s[i][2], s[i][3]));
#pragma unroll
            for (int o = 8; o >= 1; o >>= 1)
                rmax = fmaxf(rmax, __shfl_xor_sync(0xffffffffu, rmax, o));
            const float mn = fmaxf(m_i[i], rmax);
            const float alpha = __expf(m_i[i] - mn);
            m_i[i] = mn;
            float su = 0.f;
#pragma unroll
            for (int j = 0; j < 4; j++) {
                const float p = __expf(s[i][j] - mn);
                s[i][j] = p;
                su += p;
            }
#pragma unroll
            for (int o = 8; o >= 1; o >>= 1)
                su += __shfl_xor_sync(0xffffffffu, su, o);
            l_i[i] = l_i[i] * alpha + su;
#pragma unroll
            for (int j = 0; j < 4; j++) accO[i][j] *= alpha;
        }

        __syncthreads();
#pragma unroll
        for (int i = 0; i < 4; i++)
#pragma unroll
            for (int j = 0; j < 4; j++)
                Ks[(ty * 4 + i) * SP + tx * 4 + j] = s[i][j];
        __syncthreads();

#pragma unroll 4
        for (int c = 0; c < 64; c++) {
            float pr[4], vr[4];
#pragma unroll
            for (int i = 0; i < 4; i++) pr[i] = Ks[(ty * 4 + i) * SP + c];
#pragma unroll
            for (int j = 0; j < 4; j++) vr[j] = Vs[c * SP + tx * 4 + j];
#pragma unroll
            for (int i = 0; i < 4; i++)
#pragma unroll
                for (int j = 0; j < 4; j++)
                    accO[i][j] += pr[i] * vr[j];
        }
        __syncthreads();
    }

#pragma unroll
    for (int i = 0; i < 4; i++) {
        const float inv = 1.0f / l_i[i];
        const int r = qm0 + ty * 4 + i;
        float4 o4 = make_float4(accO[i][0] * inv, accO[i][1] * inv,
                                accO[i][2] * inv, accO[i][3] * inv);
        *(float4*)&g_attn[((size_t)b * SEQ + r) * EMB + h * HD + tx * 4] = o4;
    }
}

// ---------------------------------------------------------------------------
extern "C" void kernel_launch(void* const* d_in, const int* in_sizes, int n_in,
                              void* d_out, int out_size)
{
    const float* x    = (const float*)d_in[0];
    const int*   mask = (const int*)d_in[1];
    const float* wq   = (const float*)d_in[2];
    const float* wk   = (const float*)d_in[3];
    const float* wv   = (const float*)d_in[4];
    const float* wo   = (const float*)d_in[5];
    float* out = (float*)d_out;

    // hi/lo bf16 splits
    split_kernel<<<(MTOT * EMB / 4) / 256, 256>>>(x,  0, MTOT * EMB);
    split_kernel<<<(EMB * EMB / 4) / 256, 256>>>(wq, 1, EMB * EMB);
    split_kernel<<<(EMB * EMB / 4) / 256, 256>>>(wk, 2, EMB * EMB);
    split_kernel<<<(EMB * EMB / 4) / 256, 256>>>(wv, 3, EMB * EMB);
    split_kernel<<<(EMB * EMB / 4) / 256, 256>>>(wo, 4, EMB * EMB);

    // QKV projections on HMMA tensor pipe
    qkv_mma_kernel<<<dim3(MTOT / 128, EMB / 128, 3), 256>>>();

    // attention (fp32)
    const int shbytes = 3 * 64 * SP * (int)sizeof(float);
    cudaFuncSetAttribute(attn_kernel,
                         cudaFuncAttributeMaxDynamicSharedMemorySize, shbytes);
    attn_kernel<<<dim3(SEQ / 64, NH, NB), 256, shbytes>>>(mask);

    // split attention output, then O-projection on HMMA
    split_kernel<<<(MTOT * EMB / 4) / 256, 256>>>(nullptr, 5, MTOT * EMB);
    oproj_mma_kernel<<<dim3(MTOT / 128, EMB / 128, 1), 256>>>(out);
}

// round 5
// speedup vs baseline: 1.7882x; 1.1517x over previous
#include <cuda_runtime.h>
#include <cuda_bf16.h>
#include <cstdint>

#define EMB  1024
#define NH   16
#define HD   64
#define SEQ  2048
#define NB   4
#define MTOT (NB * SEQ)   // 8192

// ---------------- scratch (__device__ globals; no allocs allowed) ----------
__device__ __nv_bfloat16 g_xh[(size_t)MTOT * EMB], g_xl[(size_t)MTOT * EMB];
__device__ __nv_bfloat16 g_ah[(size_t)MTOT * EMB], g_al[(size_t)MTOT * EMB];
__device__ __nv_bfloat16 g_wh[4][(size_t)EMB * EMB], g_wl[4][(size_t)EMB * EMB];
__device__ __nv_bfloat16 g_qh[(size_t)NB * NH * SEQ * HD], g_ql[(size_t)NB * NH * SEQ * HD];
__device__ __nv_bfloat16 g_kh[(size_t)NB * NH * SEQ * HD], g_kl[(size_t)NB * NH * SEQ * HD];
__device__ __nv_bfloat16 g_vh[(size_t)NB * NH * SEQ * HD], g_vl[(size_t)NB * NH * SEQ * HD];

// ---------------- helpers ---------------------------------------------------
__device__ __forceinline__ uint32_t smem_u32(const void* p) {
    uint32_t a;
    asm("{ .reg .u64 t; cvta.to.shared.u64 t, %1; cvt.u32.u64 %0, t; }"
        : "=r"(a) : "l"(p));
    return a;
}
__device__ __forceinline__ void ldsm4(uint32_t* r, uint32_t addr) {
    asm volatile("ldmatrix.sync.aligned.m8n8.x4.shared.b16 {%0,%1,%2,%3}, [%4];"
                 : "=r"(r[0]), "=r"(r[1]), "=r"(r[2]), "=r"(r[3]) : "r"(addr));
}
__device__ __forceinline__ void ldsm4t(uint32_t* r, uint32_t addr) {
    asm volatile("ldmatrix.sync.aligned.m8n8.x4.trans.shared.b16 {%0,%1,%2,%3}, [%4];"
                 : "=r"(r[0]), "=r"(r[1]), "=r"(r[2]), "=r"(r[3]) : "r"(addr));
}
__device__ __forceinline__ void mma16816(float* c, const uint32_t* a,
                                         uint32_t b0, uint32_t b1) {
    asm volatile(
        "mma.sync.aligned.m16n8k16.row.col.f32.bf16.bf16.f32 "
        "{%0,%1,%2,%3}, {%4,%5,%6,%7}, {%8,%9}, {%0,%1,%2,%3};"
        : "+f"(c[0]), "+f"(c[1]), "+f"(c[2]), "+f"(c[3])
        : "r"(a[0]), "r"(a[1]), "r"(a[2]), "r"(a[3]), "r"(b0), "r"(b1));
}
__device__ __forceinline__ uint32_t pack_bf16(float lo, float hi) {
    uint32_t r;
    asm("cvt.rn.bf16x2.f32 %0, %1, %2;" : "=r"(r) : "f"(hi), "f"(lo));
    return r;
}
__device__ __forceinline__ float bf16_round(float x) {
    return __bfloat162float(__float2bfloat16(x));
}

// ---------------- hi/lo split prepass (x + 4 weights) -----------------------
__global__ void __launch_bounds__(256)
split_kernel(const float* __restrict__ in, int which, int n)
{
    __nv_bfloat16 *hp, *lp;
    if (which == 0) { hp = g_xh; lp = g_xl; }
    else            { hp = g_wh[which - 1]; lp = g_wl[which - 1]; }

    int i = (blockIdx.x * 256 + threadIdx.x) * 4;
    if (i >= n) return;
    float4 v = *(const float4*)(in + i);
    float h0 = bf16_round(v.x), h1 = bf16_round(v.y);
    float h2 = bf16_round(v.z), h3 = bf16_round(v.w);
    *(uint32_t*)(hp + i)     = pack_bf16(h0, h1);
    *(uint32_t*)(hp + i + 2) = pack_bf16(h2, h3);
    *(uint32_t*)(lp + i)     = pack_bf16(v.x - h0, v.y - h1);
    *(uint32_t*)(lp + i + 2) = pack_bf16(v.z - h2, v.w - h3);
}

// ---------------- HMMA split-bf16 GEMM --------------------------------------
// C[m,n] = sum_k A[m,k]*B[n,k].  128x128 CTA tile, 8 warps of 32x64, BK=32.
// MODE 0: fp32 row-major [*, EMB].  MODE 1: hi/lo bf16 scatter to [B,H,S,D].
#define TS 40

template <int MODE>
__device__ void hmma_gemm(const __nv_bfloat16* __restrict__ Ah_,
                          const __nv_bfloat16* __restrict__ Al_,
                          const __nv_bfloat16* __restrict__ Bh_,
                          const __nv_bfloat16* __restrict__ Bl_,
                          float* __restrict__ Cf,
                          __nv_bfloat16* __restrict__ Ch,
                          __nv_bfloat16* __restrict__ Cl,
                          float oscale)
{
    __shared__ __nv_bfloat16 sAh[128][TS], sAl[128][TS];
    __shared__ __nv_bfloat16 sBh[128][TS], sBl[128][TS];

    const int tid   = threadIdx.x;
    const int lane  = tid & 31;
    const int wid   = tid >> 5;
    const int warpM = wid & 3;
    const int warpN = wid >> 2;
    const int m0 = blockIdx.x * 128;
    const int n0 = blockIdx.y * 128;

    const uint32_t bAh = smem_u32(&sAh[0][0]);
    const uint32_t bAl = smem_u32(&sAl[0][0]);
    const uint32_t bBh = smem_u32(&sBh[0][0]);
    const uint32_t bBl = smem_u32(&sBl[0][0]);

    float acc[2][8][4];
#pragma unroll
    for (int mt = 0; mt < 2; mt++)
#pragma unroll
        for (int nt = 0; nt < 8; nt++)
#pragma unroll
            for (int e = 0; e < 4; e++) acc[mt][nt][e] = 0.f;

    const int a_r = lane & 15;
    const int a_c = (lane >> 4) << 3;
    const int b_r = ((lane >> 4) << 3) + (lane & 7);
    const int b_c = ((lane >> 3) & 1) << 3;

    for (int ch = 0; ch < EMB / 32; ch++) {
        const int k0 = ch * 32;
        __syncthreads();
#pragma unroll
        for (int u = tid; u < 512; u += 256) {
            const int r = u >> 2, c = (u & 3) << 3;
            *(uint4*)&sAh[r][c] = *(const uint4*)(Ah_ + (size_t)(m0 + r) * EMB + k0 + c);
            *(uint4*)&sAl[r][c] = *(const uint4*)(Al_ + (size_t)(m0 + r) * EMB + k0 + c);
            *(uint4*)&sBh[r][c] = *(const uint4*)(Bh_ + (size_t)(n0 + r) * EMB + k0 + c);
            *(uint4*)&sBl[r][c] = *(const uint4*)(Bl_ + (size_t)(n0 + r) * EMB + k0 + c);
        }
        __syncthreads();

#pragma unroll
        for (int ks = 0; ks < 2; ks++) {
            const int kb = ks << 4;
            uint32_t ah[2][4], al[2][4];
#pragma unroll
            for (int mt = 0; mt < 2; mt++) {
                const uint32_t off =
                    (uint32_t)((warpM * 32 + mt * 16 + a_r) * TS + kb + a_c) * 2;
                ldsm4(ah[mt], bAh + off);
                ldsm4(al[mt], bAl + off);
            }
#pragma unroll
            for (int ng = 0; ng < 4; ng++) {
                const uint32_t off =
                    (uint32_t)((warpN * 64 + ng * 16 + b_r) * TS + kb + b_c) * 2;
                uint32_t bh[4], bl[4];
                ldsm4(bh, bBh + off);
                ldsm4(bl, bBl + off);
#pragma unroll
                for (int mt = 0; mt < 2; mt++) {
                    mma16816(acc[mt][2 * ng],     ah[mt], bh[0], bh[1]);
                    mma16816(acc[mt][2 * ng],     ah[mt], bl[0], bl[1]);
                    mma16816(acc[mt][2 * ng],     al[mt], bh[0], bh[1]);
                    mma16816(acc[mt][2 * ng + 1], ah[mt], bh[2], bh[3]);
                    mma16816(acc[mt][2 * ng + 1], ah[mt], bl[2], bl[3]);
                    mma16816(acc[mt][2 * ng + 1], al[mt], bh[2], bh[3]);
                }
            }
        }
    }

#pragma unroll
    for (int mt = 0; mt < 2; mt++) {
#pragma unroll
        for (int nt = 0; nt < 8; nt++) {
            const int row = m0 + warpM * 32 + mt * 16 + (lane >> 2);
            const int col = n0 + warpN * 64 + nt * 8 + ((lane & 3) << 1);
#pragma unroll
            for (int half = 0; half < 2; half++) {
                const int r = row + half * 8;
                float vx = acc[mt][nt][2 * half]     * oscale;
                float vy = acc[mt][nt][2 * half + 1] * oscale;
                if (MODE == 0) {
                    *(float2*)&Cf[(size_t)r * EMB + col] = make_float2(vx, vy);
                } else {
                    const int b = r >> 11, s = r & (SEQ - 1);
                    const int h = col >> 6, d = col & (HD - 1);
                    const size_t o = ((((size_t)b * NH + h) * SEQ + s) << 6) + d;
                    float hx = bf16_round(vx), hy = bf16_round(vy);
                    *(uint32_t*)(Ch + o) = pack_bf16(hx, hy);
                    *(uint32_t*)(Cl + o) = pack_bf16(vx - hx, vy - hy);
                }
            }
        }
    }
}

__global__ void __launch_bounds__(256) qkv_mma_kernel()
{
    const int z = blockIdx.z;
    if (z == 0)
        hmma_gemm<1>(g_xh, g_xl, g_wh[0], g_wl[0], nullptr, g_qh, g_ql, 0.125f);
    else if (z == 1)
        hmma_gemm<1>(g_xh, g_xl, g_wh[1], g_wl[1], nullptr, g_kh, g_kl, 1.0f);
    else
        hmma_gemm<1>(g_xh, g_xl, g_wh[2], g_wl[2], nullptr, g_vh, g_vl, 1.0f);
}
__global__ void __launch_bounds__(256) oproj_mma_kernel(float* __restrict__ out)
{
    hmma_gemm<0>(g_ah, g_al, g_wh[3], g_wl[3], out, nullptr, nullptr, 1.0f);
}

// ---------------- HMMA flash attention --------------------------------------
// 128 q-rows per CTA (8 warps x 16 rows), K-tiles of 128. Split-bf16 MMAs.
#define AST 72                            // smem stride in halves
#define ATILE (128 * AST)                 // halves per tile
#define ASMEM (6 * ATILE * 2 + 128 * 4)   // 6 bf16 tiles + mask ints

__global__ void __launch_bounds__(256)
attn_hmma_kernel(const int* __restrict__ mask)
{
    extern __shared__ char sm[];
    __nv_bfloat16* sQh = (__nv_bfloat16*)sm;
    __nv_bfloat16* sQl = sQh + ATILE;
    __nv_bfloat16* sKh = sQl + ATILE;
    __nv_bfloat16* sKl = sKh + ATILE;
    __nv_bfloat16* sVh = sKl + ATILE;
    __nv_bfloat16* sVl = sVh + ATILE;
    int* sMask = (int*)(sVl + ATILE);

    const int tid  = threadIdx.x;
    const int lane = tid & 31;
    const int wid  = tid >> 5;
    const int qt   = blockIdx.x;
    const int h    = blockIdx.y;
    const int b    = blockIdx.z;

    const uint32_t bQh = smem_u32(sQh), bQl = smem_u32(sQl);
    const uint32_t bKh = smem_u32(sKh), bKl = smem_u32(sKl);
    const uint32_t bVh = smem_u32(sVh), bVl = smem_u32(sVl);

    const size_t hb = ((size_t)b * NH + h) * SEQ * HD;
    const int* mrow = mask + b * SEQ;

    // load Q tile (rows qt*128..+128)
    for (int u = tid; u < 1024; u += 256) {
        const int r = u >> 3, c = (u & 7) << 3;
        const size_t g = hb + (size_t)(qt * 128 + r) * HD + c;
        *(uint4*)&sQh[r * AST + c] = *(const uint4*)(g_qh + g);
        *(uint4*)&sQl[r * AST + c] = *(const uint4*)(g_ql + g);
    }

    const int a_r = lane & 15;
    const int a_c = (lane >> 4) << 3;
    const int b_r = ((lane >> 4) << 3) + (lane & 7);
    const int b_c = ((lane >> 3) & 1) << 3;
    // trans-ldmatrix lane addressing for V
    const int v_kr = ((lane >> 3) & 1) * 8 + (lane & 7);
    const int v_dc = (lane >> 4) << 3;

    const int tq   = lane & 3;
    const int row0 = qt * 128 + wid * 16 + (lane >> 2);
    const int row1 = row0 + 8;

    float m0 = -1e30f, m1 = -1e30f, l0 = 0.f, l1 = 0.f;
    float accO[8][4];
#pragma unroll
    for (int nt = 0; nt < 8; nt++)
#pragma unroll
        for (int e = 0; e < 4; e++) accO[nt][e] = 0.f;

    for (int kt = 0; kt <= qt; kt++) {
        __syncthreads();
        for (int u = tid; u < 1024; u += 256) {
            const int r = u >> 3, c = (u & 7) << 3;
            const size_t g = hb + (size_t)(kt * 128 + r) * HD + c;
            *(uint4*)&sKh[r * AST + c] = *(const uint4*)(g_kh + g);
            *(uint4*)&sKl[r * AST + c] = *(const uint4*)(g_kl + g);
            *(uint4*)&sVh[r * AST + c] = *(const uint4*)(g_vh + g);
            *(uint4*)&sVl[r * AST + c] = *(const uint4*)(g_vl + g);
        }
        if (tid < 128) sMask[tid] = mrow[kt * 128 + tid];
        __syncthreads();

        // ---- S = Q K^T (pre-scaled, fp32 accum via 3-MMA split) ----
        float sacc[16][4];
#pragma unroll
        for (int nt = 0; nt < 16; nt++)
#pragma unroll
            for (int e = 0; e < 4; e++) sacc[nt][e] = 0.f;

#pragma unroll
        for (int kc = 0; kc < 4; kc++) {
            const int kb = kc << 4;
            uint32_t qh[4], ql[4];
            {
                const uint32_t off = (uint32_t)((wid * 16 + a_r) * AST + kb + a_c) * 2;
                ldsm4(qh, bQh + off);
                ldsm4(ql, bQl + off);
            }
#pragma unroll
            for (int n2 = 0; n2 < 8; n2++) {
                const uint32_t off = (uint32_t)((n2 * 16 + b_r) * AST + kb + b_c) * 2;
                uint32_t kh4[4], kl4[4];
                ldsm4(kh4, bKh + off);
                ldsm4(kl4, bKl + off);
                mma16816(sacc[2 * n2],     qh, kh4[0], kh4[1]);
                mma16816(sacc[2 * n2],     qh, kl4[0], kl4[1]);
                mma16816(sacc[2 * n2],     ql, kh4[0], kh4[1]);
                mma16816(sacc[2 * n2 + 1], qh, kh4[2], kh4[3]);
                mma16816(sacc[2 * n2 + 1], qh, kl4[2], kl4[3]);
                mma16816(sacc[2 * n2 + 1], ql, kh4[2], kh4[3]);
            }
        }

        // ---- mask ----
#pragma unroll
        for (int nt = 0; nt < 16; nt++) {
            const int c0 = nt * 8 + tq * 2;
            const int k0 = kt * 128 + c0;
            const bool v0 = sMask[c0] != 0;
            const bool v1 = sMask[c0 + 1] != 0;
            if (!(v0 && k0     <= row0)) sacc[nt][0] = -1e30f;
            if (!(v1 && k0 + 1 <= row0)) sacc[nt][1] = -1e30f;
            if (!(v0 && k0     <= row1)) sacc[nt][2] = -1e30f;
            if (!(v1 && k0 + 1 <= row1)) sacc[nt][3] = -1e30f;
        }

        // ---- online softmax ----
        float r0 = -1e30f, r1 = -1e30f;
#pragma unroll
        for (int nt = 0; nt < 16; nt++) {
            r0 = fmaxf(r0, fmaxf(sacc[nt][0], sacc[nt][1]));
            r1 = fmaxf(r1, fmaxf(sacc[nt][2], sacc[nt][3]));
        }
        r0 = fmaxf(r0, __shfl_xor_sync(0xffffffffu, r0, 1));
        r0 = fmaxf(r0, __shfl_xor_sync(0xffffffffu, r0, 2));
        r1 = fmaxf(r1, __shfl_xor_sync(0xffffffffu, r1, 1));
        r1 = fmaxf(r1, __shfl_xor_sync(0xffffffffu, r1, 2));

        const float mn0 = fmaxf(m0, r0), mn1 = fmaxf(m1, r1);
        const float al0 = __expf(m0 - mn0), al1 = __expf(m1 - mn1);
        m0 = mn0; m1 = mn1;

        float s0 = 0.f, s1 = 0.f;
#pragma unroll
        for (int nt = 0; nt < 16; nt++) {
            sacc[nt][0] = __expf(sacc[nt][0] - mn0); s0 += sacc[nt][0];
            sacc[nt][1] = __expf(sacc[nt][1] - mn0); s0 += sacc[nt][1];
            sacc[nt][2] = __expf(sacc[nt][2] - mn1); s1 += sacc[nt][2];
            sacc[nt][3] = __expf(sacc[nt][3] - mn1); s1 += sacc[nt][3];
        }
        s0 += __shfl_xor_sync(0xffffffffu, s0, 1);
        s0 += __shfl_xor_sync(0xffffffffu, s0, 2);
        s1 += __shfl_xor_sync(0xffffffffu, s1, 1);
        s1 += __shfl_xor_sync(0xffffffffu, s1, 2);
        l0 = l0 * al0 + s0;
        l1 = l1 * al1 + s1;
#pragma unroll
        for (int nt = 0; nt < 8; nt++) {
            accO[nt][0] *= al0; accO[nt][1] *= al0;
            accO[nt][2] *= al1; accO[nt][3] *= al1;
        }

        // ---- O += P V (split P and V) ----
#pragma unroll
        for (int c2 = 0; c2 < 8; c2++) {
            const float p00 = sacc[2 * c2][0],     p01 = sacc[2 * c2][1];
            const float p02 = sacc[2 * c2][2],     p03 = sacc[2 * c2][3];
            const float p10 = sacc[2 * c2 + 1][0], p11 = sacc[2 * c2 + 1][1];
            const float p12 = sacc[2 * c2 + 1][2], p13 = sacc[2 * c2 + 1][3];
            const float h00 = bf16_round(p00), h01 = bf16_round(p01);
            const float h02 = bf16_round(p02), h03 = bf16_round(p03);
            const float h10 = bf16_round(p10), h11 = bf16_round(p11);
            const float h12 = bf16_round(p12), h13 = bf16_round(p13);
            uint32_t ph[4], pl[4];
            ph[0] = pack_bf16(h00, h01); ph[1] = pack_bf16(h02, h03);
            ph[2] = pack_bf16(h10, h11); ph[3] = pack_bf16(h12, h13);
            pl[0] = pack_bf16(p00 - h00, p01 - h01);
            pl[1] = pack_bf16(p02 - h02, p03 - h03);
            pl[2] = pack_bf16(p10 - h10, p11 - h11);
            pl[3] = pack_bf16(p12 - h12, p13 - h13);

#pragma unroll
            for (int dp = 0; dp < 4; dp++) {
                const uint32_t off =
                    (uint32_t)((c2 * 16 + v_kr) * AST + dp * 16 + v_dc) * 2;
                uint32_t vh4[4], vl4[4];
                ldsm4t(vh4, bVh + off);
                ldsm4t(vl4, bVl + off);
                mma16816(accO[2 * dp],     ph, vh4[0], vh4[1]);
                mma16816(accO[2 * dp],     ph, vl4[0], vl4[1]);
                mma16816(accO[2 * dp],     pl, vh4[0], vh4[1]);
                mma16816(accO[2 * dp + 1], ph, vh4[2], vh4[3]);
                mma16816(accO[2 * dp + 1], ph, vl4[2], vl4[3]);
                mma16816(accO[2 * dp + 1], pl, vh4[2], vh4[3]);
            }
        }
    }

    // ---- epilogue: hi/lo bf16 into [B, S, E] for the O-projection ----
    const float i0 = 1.f / l0, i1 = 1.f / l1;
    const size_t ob0 = ((size_t)b * SEQ + row0) * EMB + h * HD;
    const size_t ob1 = ((size_t)b * SEQ + row1) * EMB + h * HD;
#pragma unroll
    for (int nt = 0; nt < 8; nt++) {
        const int col = nt * 8 + tq * 2;
        const float x0 = accO[nt][0] * i0, y0 = accO[nt][1] * i0;
        const float x1 = accO[nt][2] * i1, y1 = accO[nt][3] * i1;
        const float hx0 = bf16_round(x0), hy0 = bf16_round(y0);
        const float hx1 = bf16_round(x1), hy1 = bf16_round(y1);
        *(uint32_t*)(g_ah + ob0 + col) = pack_bf16(hx0, hy0);
        *(uint32_t*)(g_al + ob0 + col) = pack_bf16(x0 - hx0, y0 - hy0);
        *(uint32_t*)(g_ah + ob1 + col) = pack_bf16(hx1, hy1);
        *(uint32_t*)(g_al + ob1 + col) = pack_bf16(x1 - hx1, y1 - hy1);
    }
}

// ---------------------------------------------------------------------------
extern "C" void kernel_launch(void* const* d_in, const int* in_sizes, int n_in,
                              void* d_out, int out_size)
{
    const float* x    = (const float*)d_in[0];
    const int*   mask = (const int*)d_in[1];
    const float* wq   = (const float*)d_in[2];
    const float* wk   = (const float*)d_in[3];
    const float* wv   = (const float*)d_in[4];
    const float* wo   = (const float*)d_in[5];
    float* out = (float*)d_out;

    split_kernel<<<(MTOT * EMB / 4) / 256, 256>>>(x,  0, MTOT * EMB);
    split_kernel<<<(EMB * EMB / 4) / 256, 256>>>(wq, 1, EMB * EMB);
    split_kernel<<<(EMB * EMB / 4) / 256, 256>>>(wk, 2, EMB * EMB);
    split_kernel<<<(EMB * EMB / 4) / 256, 256>>>(wv, 3, EMB * EMB);
    split_kernel<<<(EMB * EMB / 4) / 256, 256>>>(wo, 4, EMB * EMB);

    qkv_mma_kernel<<<dim3(MTOT / 128, EMB / 128, 3), 256>>>();

    cudaFuncSetAttribute(attn_hmma_kernel,
                         cudaFuncAttributeMaxDynamicSharedMemorySize, ASMEM);
    attn_hmma_kernel<<<dim3(SEQ / 128, NH, NB), 256, ASMEM>>>(mask);

    oproj_mma_kernel<<<dim3(MTOT / 128, EMB / 128, 1), 256>>>(out);
}

// round 6
// speedup vs baseline: 3.0074x; 1.6818x over previous
#include <cuda_runtime.h>
#include <cuda_bf16.h>
#include <cstdint>

#define EMB  1024
#define NH   16
#define HD   64
#define SEQ  2048
#define NB   4
#define MTOT (NB * SEQ)   // 8192

// ---------------- scratch (__device__ globals; no allocs allowed) ----------
__device__ __nv_bfloat16 g_xh[(size_t)MTOT * EMB], g_xl[(size_t)MTOT * EMB];
__device__ __nv_bfloat16 g_ah[(size_t)MTOT * EMB], g_al[(size_t)MTOT * EMB];
__device__ __nv_bfloat16 g_wh[4][(size_t)EMB * EMB], g_wl[4][(size_t)EMB * EMB];
__device__ __nv_bfloat16 g_qh[(size_t)NB * NH * SEQ * HD], g_ql[(size_t)NB * NH * SEQ * HD];
__device__ __nv_bfloat16 g_kh[(size_t)NB * NH * SEQ * HD], g_kl[(size_t)NB * NH * SEQ * HD];
__device__ __nv_bfloat16 g_vh[(size_t)NB * NH * SEQ * HD], g_vl[(size_t)NB * NH * SEQ * HD];

// ---------------- helpers ---------------------------------------------------
__device__ __forceinline__ uint32_t smem_u32(const void* p) {
    uint32_t a;
    asm("{ .reg .u64 t; cvta.to.shared.u64 t, %1; cvt.u32.u64 %0, t; }"
        : "=r"(a) : "l"(p));
    return a;
}
__device__ __forceinline__ void ldsm4(uint32_t* r, uint32_t addr) {
    asm volatile("ldmatrix.sync.aligned.m8n8.x4.shared.b16 {%0,%1,%2,%3}, [%4];"
                 : "=r"(r[0]), "=r"(r[1]), "=r"(r[2]), "=r"(r[3]) : "r"(addr));
}
__device__ __forceinline__ void ldsm4t(uint32_t* r, uint32_t addr) {
    asm volatile("ldmatrix.sync.aligned.m8n8.x4.trans.shared.b16 {%0,%1,%2,%3}, [%4];"
                 : "=r"(r[0]), "=r"(r[1]), "=r"(r[2]), "=r"(r[3]) : "r"(addr));
}
__device__ __forceinline__ void mma16816(float* c, const uint32_t* a,
                                         uint32_t b0, uint32_t b1) {
    asm volatile(
        "mma.sync.aligned.m16n8k16.row.col.f32.bf16.bf16.f32 "
        "{%0,%1,%2,%3}, {%4,%5,%6,%7}, {%8,%9}, {%0,%1,%2,%3};"
        : "+f"(c[0]), "+f"(c[1]), "+f"(c[2]), "+f"(c[3])
        : "r"(a[0]), "r"(a[1]), "r"(a[2]), "r"(a[3]), "r"(b0), "r"(b1));
}
__device__ __forceinline__ uint32_t pack_bf16(float lo, float hi) {
    uint32_t r;
    asm("cvt.rn.bf16x2.f32 %0, %1, %2;" : "=r"(r) : "f"(hi), "f"(lo));
    return r;
}
__device__ __forceinline__ float bf16_round(float x) {
    return __bfloat162float(__float2bfloat16(x));
}
__device__ __forceinline__ void cp16(uint32_t saddr, const void* g) {
    asm volatile("cp.async.cg.shared.global [%0], [%1], 16;"
                 :: "r"(saddr), "l"(g) : "memory");
}
__device__ __forceinline__ void cp_wait_all() {
    asm volatile("cp.async.commit_group;" ::: "memory");
    asm volatile("cp.async.wait_group 0;" ::: "memory");
}

// ---------------- hi/lo split prepass (x + 4 weights) -----------------------
__global__ void __launch_bounds__(256)
split_kernel(const float* __restrict__ in, int which, int n)
{
    __nv_bfloat16 *hp, *lp;
    if (which == 0) { hp = g_xh; lp = g_xl; }
    else            { hp = g_wh[which - 1]; lp = g_wl[which - 1]; }

    int i = (blockIdx.x * 256 + threadIdx.x) * 4;
    if (i >= n) return;
    float4 v = *(const float4*)(in + i);
    float h0 = bf16_round(v.x), h1 = bf16_round(v.y);
    float h2 = bf16_round(v.z), h3 = bf16_round(v.w);
    *(uint32_t*)(hp + i)     = pack_bf16(h0, h1);
    *(uint32_t*)(hp + i + 2) = pack_bf16(h2, h3);
    *(uint32_t*)(lp + i)     = pack_bf16(v.x - h0, v.y - h1);
    *(uint32_t*)(lp + i + 2) = pack_bf16(v.z - h2, v.w - h3);
}

// ---------------- HMMA split-bf16 GEMM (unchanged, known-good) ---------------
#define TS 40

template <int MODE>
__device__ void hmma_gemm(const __nv_bfloat16* __restrict__ Ah_,
                          const __nv_bfloat16* __restrict__ Al_,
                          const __nv_bfloat16* __restrict__ Bh_,
                          const __nv_bfloat16* __restrict__ Bl_,
                          float* __restrict__ Cf,
                          __nv_bfloat16* __restrict__ Ch,
                          __nv_bfloat16* __restrict__ Cl,
                          float oscale)
{
    __shared__ __nv_bfloat16 sAh[128][TS], sAl[128][TS];
    __shared__ __nv_bfloat16 sBh[128][TS], sBl[128][TS];

    const int tid   = threadIdx.x;
    const int lane  = tid & 31;
    const int wid   = tid >> 5;
    const int warpM = wid & 3;
    const int warpN = wid >> 2;
    const int m0 = blockIdx.x * 128;
    const int n0 = blockIdx.y * 128;

    const uint32_t bAh = smem_u32(&sAh[0][0]);
    const uint32_t bAl = smem_u32(&sAl[0][0]);
    const uint32_t bBh = smem_u32(&sBh[0][0]);
    const uint32_t bBl = smem_u32(&sBl[0][0]);

    float acc[2][8][4];
#pragma unroll
    for (int mt = 0; mt < 2; mt++)
#pragma unroll
        for (int nt = 0; nt < 8; nt++)
#pragma unroll
            for (int e = 0; e < 4; e++) acc[mt][nt][e] = 0.f;

    const int a_r = lane & 15;
    const int a_c = (lane >> 4) << 3;
    const int b_r = ((lane >> 4) << 3) + (lane & 7);
    const int b_c = ((lane >> 3) & 1) << 3;

    for (int ch = 0; ch < EMB / 32; ch++) {
        const int k0 = ch * 32;
        __syncthreads();
#pragma unroll
        for (int u = tid; u < 512; u += 256) {
            const int r = u >> 2, c = (u & 3) << 3;
            *(uint4*)&sAh[r][c] = *(const uint4*)(Ah_ + (size_t)(m0 + r) * EMB + k0 + c);
            *(uint4*)&sAl[r][c] = *(const uint4*)(Al_ + (size_t)(m0 + r) * EMB + k0 + c);
            *(uint4*)&sBh[r][c] = *(const uint4*)(Bh_ + (size_t)(n0 + r) * EMB + k0 + c);
            *(uint4*)&sBl[r][c] = *(const uint4*)(Bl_ + (size_t)(n0 + r) * EMB + k0 + c);
        }
        __syncthreads();

#pragma unroll
        for (int ks = 0; ks < 2; ks++) {
            const int kb = ks << 4;
            uint32_t ah[2][4], al[2][4];
#pragma unroll
            for (int mt = 0; mt < 2; mt++) {
                const uint32_t off =
                    (uint32_t)((warpM * 32 + mt * 16 + a_r) * TS + kb + a_c) * 2;
                ldsm4(ah[mt], bAh + off);
                ldsm4(al[mt], bAl + off);
            }
#pragma unroll
            for (int ng = 0; ng < 4; ng++) {
                const uint32_t off =
                    (uint32_t)((warpN * 64 + ng * 16 + b_r) * TS + kb + b_c) * 2;
                uint32_t bh[4], bl[4];
                ldsm4(bh, bBh + off);
                ldsm4(bl, bBl + off);
#pragma unroll
                for (int mt = 0; mt < 2; mt++) {
                    mma16816(acc[mt][2 * ng],     ah[mt], bh[0], bh[1]);
                    mma16816(acc[mt][2 * ng],     ah[mt], bl[0], bl[1]);
                    mma16816(acc[mt][2 * ng],     al[mt], bh[0], bh[1]);
                    mma16816(acc[mt][2 * ng + 1], ah[mt], bh[2], bh[3]);
                    mma16816(acc[mt][2 * ng + 1], ah[mt], bl[2], bl[3]);
                    mma16816(acc[mt][2 * ng + 1], al[mt], bh[2], bh[3]);
                }
            }
        }
    }

#pragma unroll
    for (int mt = 0; mt < 2; mt++) {
#pragma unroll
        for (int nt = 0; nt < 8; nt++) {
            const int row = m0 + warpM * 32 + mt * 16 + (lane >> 2);
            const int col = n0 + warpN * 64 + nt * 8 + ((lane & 3) << 1);
#pragma unroll
            for (int half = 0; half < 2; half++) {
                const int r = row + half * 8;
                float vx = acc[mt][nt][2 * half]     * oscale;
                float vy = acc[mt][nt][2 * half + 1] * oscale;
                if (MODE == 0) {
                    *(float2*)&Cf[(size_t)r * EMB + col] = make_float2(vx, vy);
                } else {
                    const int b = r >> 11, s = r & (SEQ - 1);
                    const int h = col >> 6, d = col & (HD - 1);
                    const size_t o = ((((size_t)b * NH + h) * SEQ + s) << 6) + d;
                    float hx = bf16_round(vx), hy = bf16_round(vy);
                    *(uint32_t*)(Ch + o) = pack_bf16(hx, hy);
                    *(uint32_t*)(Cl + o) = pack_bf16(vx - hx, vy - hy);
                }
            }
        }
    }
}

__global__ void __launch_bounds__(256) qkv_mma_kernel()
{
    const int z = blockIdx.z;
    if (z == 0)
        hmma_gemm<1>(g_xh, g_xl, g_wh[0], g_wl[0], nullptr, g_qh, g_ql, 0.125f);
    else if (z == 1)
        hmma_gemm<1>(g_xh, g_xl, g_wh[1], g_wl[1], nullptr, g_kh, g_kl, 1.0f);
    else
        hmma_gemm<1>(g_xh, g_xl, g_wh[2], g_wl[2], nullptr, g_vh, g_vl, 1.0f);
}
__global__ void __launch_bounds__(256) oproj_mma_kernel(float* __restrict__ out)
{
    hmma_gemm<0>(g_ah, g_al, g_wh[3], g_wl[3], out, nullptr, nullptr, 1.0f);
}

// ---------------- HMMA flash attention v2 ------------------------------------
// 128 q-rows per CTA, 8 warps x 16 rows, K-tiles of 128 processed in two
// 64-column halves (caps sacc at 32 regs). XOR-swizzled 16KB tiles (128B rows),
// cp.async loads, 2 CTAs/SM.
#define ATB 16384                          // bytes per 128x64-half tile
#define ASMEM (6 * ATB + 512)

// swizzled byte offset of 16B unit u (0..7) in row r (0..127)
__device__ __forceinline__ uint32_t swz(int r, int u) {
    return (uint32_t)(r * 128 + (((u ^ r) & 7) << 4) + (u & ~7) * 16);
}

__global__ void __launch_bounds__(256, 2)
attn_hmma_kernel(const int* __restrict__ mask)
{
    extern __shared__ char sm[];
    const uint32_t bQh = smem_u32(sm);
    const uint32_t bQl = bQh + ATB;
    const uint32_t bKh = bQh + 2 * ATB;
    const uint32_t bKl = bQh + 3 * ATB;
    const uint32_t bVh = bQh + 4 * ATB;
    const uint32_t bVl = bQh + 5 * ATB;
    int* sMask = (int*)(sm + 6 * ATB);

    const int tid  = threadIdx.x;
    const int lane = tid & 31;
    const int wid  = tid >> 5;
    const int qt   = blockIdx.x;
    const int h    = blockIdx.y;
    const int b    = blockIdx.z;

    const size_t hb = ((size_t)b * NH + h) * SEQ * HD;
    const int* mrow = mask + b * SEQ;

    // async-load Q tile once
    for (int u = tid; u < 1024; u += 256) {
        const int r = u >> 3, c = u & 7;
        const uint32_t sw = swz(r, c);
        const size_t g = hb + (size_t)(qt * 128 + r) * HD + c * 8;
        cp16(bQh + sw, g_qh + g);
        cp16(bQl + sw, g_ql + g);
    }

    const int a_r = lane & 15;
    const int a_u = lane >> 4;               // Q: unit offset 0/1 within kc
    const int b_r = ((lane >> 4) << 3) + (lane & 7);
    const int b_u = (lane >> 3) & 1;         // K: unit offset
    const int v_kr = ((lane >> 3) & 1) * 8 + (lane & 7);
    const int v_u  = lane >> 4;              // V: unit offset within dp

    const int tq   = lane & 3;
    const int row0 = qt * 128 + wid * 16 + (lane >> 2);
    const int row1 = row0 + 8;
    const int qrow = wid * 16 + a_r;

    float m0 = -1e30f, m1 = -1e30f, l0 = 0.f, l1 = 0.f;
    float accO[8][4];
#pragma unroll
    for (int nt = 0; nt < 8; nt++)
#pragma unroll
        for (int e = 0; e < 4; e++) accO[nt][e] = 0.f;

    for (int kt = 0; kt <= qt; kt++) {
        __syncthreads();       // prior compute done before overwriting K/V
        for (int u = tid; u < 1024; u += 256) {
            const int r = u >> 3, c = u & 7;
            const uint32_t sw = swz(r, c);
            const size_t g = hb + (size_t)(kt * 128 + r) * HD + c * 8;
            cp16(bKh + sw, g_kh + g);
            cp16(bKl + sw, g_kl + g);
            cp16(bVh + sw, g_vh + g);
            cp16(bVl + sw, g_vl + g);
        }
        if (tid < 128) sMask[tid] = mrow[kt * 128 + tid];
        cp_wait_all();
        __syncthreads();

#pragma unroll
        for (int nh = 0; nh < 2; nh++) {
            // ---- S half = Q K^T ----
            float sacc[8][4];
#pragma unroll
            for (int nt = 0; nt < 8; nt++)
#pragma unroll
                for (int e = 0; e < 4; e++) sacc[nt][e] = 0.f;

#pragma unroll
            for (int kc = 0; kc < 4; kc++) {
                uint32_t qh[4], ql[4];
                const uint32_t qoff = swz(qrow, kc * 2 + a_u);
                ldsm4(qh, bQh + qoff);
                ldsm4(ql, bQl + qoff);
#pragma unroll
                for (int n2 = 0; n2 < 4; n2++) {
                    const int krow = (nh * 4 + n2) * 16 + b_r;
                    const uint32_t koff = swz(krow, kc * 2 + b_u);
                    uint32_t kh4[4], kl4[4];
                    ldsm4(kh4, bKh + koff);
                    ldsm4(kl4, bKl + koff);
                    mma16816(sacc[2 * n2],     qh, kh4[0], kh4[1]);
                    mma16816(sacc[2 * n2],     qh, kl4[0], kl4[1]);
                    mma16816(sacc[2 * n2],     ql, kh4[0], kh4[1]);
                    mma16816(sacc[2 * n2 + 1], qh, kh4[2], kh4[3]);
                    mma16816(sacc[2 * n2 + 1], qh, kl4[2], kl4[3]);
                    mma16816(sacc[2 * n2 + 1], ql, kh4[2], kh4[3]);
                }
            }

            // ---- mask ----
#pragma unroll
            for (int nt = 0; nt < 8; nt++) {
                const int c0 = nh * 64 + nt * 8 + tq * 2;
                const int k0 = kt * 128 + c0;
                const bool v0 = sMask[c0] != 0;
                const bool v1 = sMask[c0 + 1] != 0;
                if (!(v0 && k0     <= row0)) sacc[nt][0] = -1e30f;
                if (!(v1 && k0 + 1 <= row0)) sacc[nt][1] = -1e30f;
                if (!(v0 && k0     <= row1)) sacc[nt][2] = -1e30f;
                if (!(v1 && k0 + 1 <= row1)) sacc[nt][3] = -1e30f;
            }

            // ---- online softmax update for this half ----
            float r0 = -1e30f, r1 = -1e30f;
#pragma unroll
            for (int nt = 0; nt < 8; nt++) {
                r0 = fmaxf(r0, fmaxf(sacc[nt][0], sacc[nt][1]));
                r1 = fmaxf(r1, fmaxf(sacc[nt][2], sacc[nt][3]));
            }
            r0 = fmaxf(r0, __shfl_xor_sync(0xffffffffu, r0, 1));
            r0 = fmaxf(r0, __shfl_xor_sync(0xffffffffu, r0, 2));
            r1 = fmaxf(r1, __shfl_xor_sync(0xffffffffu, r1, 1));
            r1 = fmaxf(r1, __shfl_xor_sync(0xffffffffu, r1, 2));

            const float mn0 = fmaxf(m0, r0), mn1 = fmaxf(m1, r1);
            const float al0 = __expf(m0 - mn0), al1 = __expf(m1 - mn1);
            m0 = mn0; m1 = mn1;

            float s0 = 0.f, s1 = 0.f;
#pragma unroll
            for (int nt = 0; nt < 8; nt++) {
                sacc[nt][0] = __expf(sacc[nt][0] - mn0); s0 += sacc[nt][0];
                sacc[nt][1] = __expf(sacc[nt][1] - mn0); s0 += sacc[nt][1];
                sacc[nt][2] = __expf(sacc[nt][2] - mn1); s1 += sacc[nt][2];
                sacc[nt][3] = __expf(sacc[nt][3] - mn1); s1 += sacc[nt][3];
            }
            s0 += __shfl_xor_sync(0xffffffffu, s0, 1);
            s0 += __shfl_xor_sync(0xffffffffu, s0, 2);
            s1 += __shfl_xor_sync(0xffffffffu, s1, 1);
            s1 += __shfl_xor_sync(0xffffffffu, s1, 2);
            l0 = l0 * al0 + s0;
            l1 = l1 * al1 + s1;
#pragma unroll
            for (int nt = 0; nt < 8; nt++) {
                accO[nt][0] *= al0; accO[nt][1] *= al0;
                accO[nt][2] *= al1; accO[nt][3] *= al1;
            }

            // ---- O += P V for this half ----
#pragma unroll
            for (int c2l = 0; c2l < 4; c2l++) {
                const int c2 = nh * 4 + c2l;
                const float p00 = sacc[2 * c2l][0],     p01 = sacc[2 * c2l][1];
                const float p02 = sacc[2 * c2l][2],     p03 = sacc[2 * c2l][3];
                const float p10 = sacc[2 * c2l + 1][0], p11 = sacc[2 * c2l + 1][1];
                const float p12 = sacc[2 * c2l + 1][2], p13 = sacc[2 * c2l + 1][3];
                const float h00 = bf16_round(p00), h01 = bf16_round(p01);
                const float h02 = bf16_round(p02), h03 = bf16_round(p03);
                const float h10 = bf16_round(p10), h11 = bf16_round(p11);
                const float h12 = bf16_round(p12), h13 = bf16_round(p13);
                uint32_t ph[4], pl[4];
                ph[0] = pack_bf16(h00, h01); ph[1] = pack_bf16(h02, h03);
                ph[2] = pack_bf16(h10, h11); ph[3] = pack_bf16(h12, h13);
                pl[0] = pack_bf16(p00 - h00, p01 - h01);
                pl[1] = pack_bf16(p02 - h02, p03 - h03);
                pl[2] = pack_bf16(p10 - h10, p11 - h11);
                pl[3] = pack_bf16(p12 - h12, p13 - h13);

#pragma unroll
                for (int dp = 0; dp < 4; dp++) {
                    const int vrow = c2 * 16 + v_kr;
                    const uint32_t voff = swz(vrow, dp * 2 + v_u);
                    uint32_t vh4[4], vl4[4];
                    ldsm4t(vh4, bVh + voff);
                    ldsm4t(vl4, bVl + voff);
                    mma16816(accO[2 * dp],     ph, vh4[0], vh4[1]);
                    mma16816(accO[2 * dp],     ph, vl4[0], vl4[1]);
                    mma16816(accO[2 * dp],     pl, vh4[0], vh4[1]);
                    mma16816(accO[2 * dp + 1], ph, vh4[2], vh4[3]);
                    mma16816(accO[2 * dp + 1], ph, vl4[2], vl4[3]);
                    mma16816(accO[2 * dp + 1], pl, vh4[2], vh4[3]);
                }
            }
        }
    }

    // ---- epilogue: hi/lo bf16 into [B, S, E] for the O-projection ----
    const float i0 = 1.f / l0, i1 = 1.f / l1;
    const size_t ob0 = ((size_t)b * SEQ + row0) * EMB + h * HD;
    const size_t ob1 = ((size_t)b * SEQ + row1) * EMB + h * HD;
#pragma unroll
    for (int nt = 0; nt < 8; nt++) {
        const int col = nt * 8 + tq * 2;
        const float x0 = accO[nt][0] * i0, y0 = accO[nt][1] * i0;
        const float x1 = accO[nt][2] * i1, y1 = accO[nt][3] * i1;
        const float hx0 = bf16_round(x0), hy0 = bf16_round(y0);
        const float hx1 = bf16_round(x1), hy1 = bf16_round(y1);
        *(uint32_t*)(g_ah + ob0 + col) = pack_bf16(hx0, hy0);
        *(uint32_t*)(g_al + ob0 + col) = pack_bf16(x0 - hx0, y0 - hy0);
        *(uint32_t*)(g_ah + ob1 + col) = pack_bf16(hx1, hy1);
        *(uint32_t*)(g_al + ob1 + col) = pack_bf16(x1 - hx1, y1 - hy1);
    }
}

// ---------------------------------------------------------------------------
extern "C" void kernel_launch(void* const* d_in, const int* in_sizes, int n_in,
                              void* d_out, int out_size)
{
    const float* x    = (const float*)d_in[0];
    const int*   mask = (const int*)d_in[1];
    const float* wq   = (const float*)d_in[2];
    const float* wk   = (const float*)d_in[3];
    const float* wv   = (const float*)d_in[4];
    const float* wo   = (const float*)d_in[5];
    float* out = (float*)d_out;

    split_kernel<<<(MTOT * EMB / 4) / 256, 256>>>(x,  0, MTOT * EMB);
    split_kernel<<<(EMB * EMB / 4) / 256, 256>>>(wq, 1, EMB * EMB);
    split_kernel<<<(EMB * EMB / 4) / 256, 256>>>(wk, 2, EMB * EMB);
    split_kernel<<<(EMB * EMB / 4) / 256, 256>>>(wv, 3, EMB * EMB);
    split_kernel<<<(EMB * EMB / 4) / 256, 256>>>(wo, 4, EMB * EMB);

    qkv_mma_kernel<<<dim3(MTOT / 128, EMB / 128, 3), 256>>>();

    cudaFuncSetAttribute(attn_hmma_kernel,
                         cudaFuncAttributeMaxDynamicSharedMemorySize, ASMEM);
    attn_hmma_kernel<<<dim3(SEQ / 128, NH, NB), 256, ASMEM>>>(mask);

    oproj_mma_kernel<<<dim3(MTOT / 128, EMB / 128, 1), 256>>>(out);
}